// round 1
// baseline (speedup 1.0000x reference)
#include <cuda_runtime.h>
#include <cuda_bf16.h>
#include <math.h>

// ---------------------------------------------------------------------------
// Problem constants
// ---------------------------------------------------------------------------
#define T_TOK   8192
#define HID     2048
#define NH      16
#define HD      128
#define INNER   2048          // NH*HD
#define QKV_W   6144          // 3*INNER
#define NCHUNK  64            // T/128
#define CHUNK   128
#define EPS     1e-5f
#define QSCALE  0.08838834764831845f   // 128^-0.5

// ---------------------------------------------------------------------------
// Device scratch (static globals: allocation-free rule)
// ---------------------------------------------------------------------------
__device__ float g_qkv [T_TOK * QKV_W];            // 192 MiB: silu(x@Wqkv), q/k rope'd in place
__device__ float g_gate[T_TOK * INNER];            // 64 MiB: x@Wg, then overwritten with gated value
__device__ float g_o   [T_TOK * INNER];            // 64 MiB: attention output
__device__ float g_kvp [NCHUNK * NH * HD * HD];    // 64 MiB: per-chunk KV outer products
__device__ float g_S   [NCHUNK * NH * HD * HD];    // 64 MiB: exclusive prefix state per chunk

// ---------------------------------------------------------------------------
// Generic fp32 SGEMM: C[M,N] = act(A[M,K] @ B[K,N])
// 128x128 block tile, BK=16, 256 threads, 8x8 microtile, prefetched
// ACT: 0 = none, 1 = silu
// ---------------------------------------------------------------------------
template<int ACT>
__global__ __launch_bounds__(256, 2)
void sgemm128(const float* __restrict__ A, const float* __restrict__ B,
              float* __restrict__ C, int M, int N, int K)
{
    __shared__ float As[16][128];   // transposed: As[k][m]
    __shared__ float Bs[16][128];   // natural:    Bs[k][n]

    const int bm = blockIdx.y * 128;
    const int bn = blockIdx.x * 128;
    const int tid = threadIdx.x;
    const int tx = tid & 15;        // 0..15 -> N microtile
    const int ty = tid >> 4;        // 0..15 -> M microtile

    // A tile loader: 128 rows x 16 cols, each thread 2 float4
    const int a_row = tid >> 2;            // 0..63 (and +64)
    const int a_col = (tid & 3) << 2;      // 0,4,8,12
    // B tile loader: 16 rows x 128 cols, each thread 2 float4
    const int b_row = tid >> 5;            // 0..7 (and +8)
    const int b_col = (tid & 31) << 2;

    const float* Ap = A + (long)(bm + a_row) * K + a_col;
    const float* Ap2 = Ap + (long)64 * K;
    const float* Bp = B + (long)b_row * N + bn + b_col;
    const float* Bp2 = Bp + (long)8 * N;

    float4 a0 = *(const float4*)(Ap);
    float4 a1 = *(const float4*)(Ap2);
    float4 b0 = *(const float4*)(Bp);
    float4 b1 = *(const float4*)(Bp2);

    float acc[8][8];
    #pragma unroll
    for (int i = 0; i < 8; i++)
        #pragma unroll
        for (int j = 0; j < 8; j++) acc[i][j] = 0.f;

    for (int k0 = 0; k0 < K; k0 += 16) {
        // store staged tile
        As[a_col+0][a_row]    = a0.x; As[a_col+1][a_row]    = a0.y;
        As[a_col+2][a_row]    = a0.z; As[a_col+3][a_row]    = a0.w;
        As[a_col+0][a_row+64] = a1.x; As[a_col+1][a_row+64] = a1.y;
        As[a_col+2][a_row+64] = a1.z; As[a_col+3][a_row+64] = a1.w;
        *(float4*)&Bs[b_row][b_col]   = b0;
        *(float4*)&Bs[b_row+8][b_col] = b1;
        __syncthreads();

        // prefetch next tile while computing this one
        if (k0 + 16 < K) {
            a0 = *(const float4*)(Ap  + k0 + 16);
            a1 = *(const float4*)(Ap2 + k0 + 16);
            b0 = *(const float4*)(Bp  + (long)(k0 + 16) * N);
            b1 = *(const float4*)(Bp2 + (long)(k0 + 16) * N);
        }

        #pragma unroll
        for (int kk = 0; kk < 16; kk++) {
            float a[8], b[8];
            *(float4*)&a[0] = *(const float4*)&As[kk][ty*8];
            *(float4*)&a[4] = *(const float4*)&As[kk][ty*8+4];
            *(float4*)&b[0] = *(const float4*)&Bs[kk][tx*8];
            *(float4*)&b[4] = *(const float4*)&Bs[kk][tx*8+4];
            #pragma unroll
            for (int i = 0; i < 8; i++)
                #pragma unroll
                for (int j = 0; j < 8; j++)
                    acc[i][j] += a[i] * b[j];
        }
        __syncthreads();
    }

    // epilogue
    #pragma unroll
    for (int i = 0; i < 8; i++) {
        float* Cp = C + (long)(bm + ty*8 + i) * N + bn + tx*8;
        float4 r0, r1;
        float v[8];
        #pragma unroll
        for (int j = 0; j < 8; j++) {
            float x = acc[i][j];
            if (ACT == 1) x = x / (1.f + expf(-x));   // silu
            v[j] = x;
        }
        r0.x = v[0]; r0.y = v[1]; r0.z = v[2]; r0.w = v[3];
        r1.x = v[4]; r1.y = v[5]; r1.z = v[6]; r1.w = v[7];
        *(float4*)(Cp)     = r0;
        *(float4*)(Cp + 4) = r1;
    }
}

// ---------------------------------------------------------------------------
// Per-(token, head) RMSNorm + RoPE (+ q scale), in place on g_qkv
// grid(T, H), 64 threads; thread j handles dims j and j+64 (rope pair)
// ---------------------------------------------------------------------------
__global__ void qk_rope_kernel(float* __restrict__ qkv,
                               const int* __restrict__ pos,
                               const float* __restrict__ qw,
                               const float* __restrict__ kw)
{
    const int t = blockIdx.x, h = blockIdx.y;
    const int j = threadIdx.x;              // 0..63
    float* qp = qkv + (long)t * QKV_W + h * HD;
    float* kp = qp + INNER;

    float q1 = qp[j], q2 = qp[j + 64];
    float k1 = kp[j], k2 = kp[j + 64];

    float sq = q1*q1 + q2*q2;
    float sk = k1*k1 + k2*k2;
    #pragma unroll
    for (int o = 16; o; o >>= 1) {
        sq += __shfl_xor_sync(0xffffffffu, sq, o);
        sk += __shfl_xor_sync(0xffffffffu, sk, o);
    }
    __shared__ float red[4];
    const int w = j >> 5, lane = j & 31;
    if (lane == 0) { red[w] = sq; red[2 + w] = sk; }
    __syncthreads();
    const float rq = rsqrtf((red[0] + red[1]) * (1.f / 128.f) + EPS);
    const float rk = rsqrtf((red[2] + red[3]) * (1.f / 128.f) + EPS);

    q1 = q1 * rq * qw[j]; q2 = q2 * rq * qw[j + 64];
    k1 = k1 * rk * kw[j]; k2 = k2 * rk * kw[j + 64];

    const float inv = powf(600000.0f, -(float)j * (1.0f / 64.0f));
    const float ang = (float)pos[t] * inv;
    float s, c;
    sincosf(ang, &s, &c);

    qp[j]      = (q1 * c - q2 * s) * QSCALE;
    qp[j + 64] = (q2 * c + q1 * s) * QSCALE;
    kp[j]      =  k1 * c - k2 * s;
    kp[j + 64] =  k2 * c + k1 * s;
}

// ---------------------------------------------------------------------------
// Per-(chunk, head) KV outer product: KV[d][e] = sum_j k[j][d] * v[j][e]
// grid(NCHUNK, NH), 256 threads, dyn smem = 2 * 64KB
// ---------------------------------------------------------------------------
__global__ __launch_bounds__(256, 1)
void kv_outer_kernel(const float* __restrict__ qkv, float* __restrict__ KV)
{
    extern __shared__ float sm[];
    float* sK = sm;            // [j][d]
    float* sV = sm + 16384;    // [j][e]

    const int c = blockIdx.x, h = blockIdx.y;
    const int t0 = c * CHUNK;
    const int tid = threadIdx.x, tx = tid & 15, ty = tid >> 4;

    const float* kg = qkv + (long)t0 * QKV_W + h * HD + INNER;
    const float* vg = kg + INNER;

    #pragma unroll
    for (int r = 0; r < 16; r++) {
        int idx = r * 256 + tid;            // 0..4095
        int row = idx >> 5;
        int col = (idx & 31) << 2;
        *(float4*)&sK[row * 128 + col] = *(const float4*)(kg + (long)row * QKV_W + col);
        *(float4*)&sV[row * 128 + col] = *(const float4*)(vg + (long)row * QKV_W + col);
    }
    __syncthreads();

    float acc[8][8];
    #pragma unroll
    for (int i = 0; i < 8; i++)
        #pragma unroll
        for (int j = 0; j < 8; j++) acc[i][j] = 0.f;

    for (int j = 0; j < 128; j++) {
        float a[8], b[8];
        *(float4*)&a[0] = *(const float4*)&sK[j * 128 + ty*8];
        *(float4*)&a[4] = *(const float4*)&sK[j * 128 + ty*8 + 4];
        *(float4*)&b[0] = *(const float4*)&sV[j * 128 + tx*8];
        *(float4*)&b[4] = *(const float4*)&sV[j * 128 + tx*8 + 4];
        #pragma unroll
        for (int i = 0; i < 8; i++)
            #pragma unroll
            for (int e = 0; e < 8; e++)
                acc[i][e] += a[i] * b[e];
    }

    float* out = KV + ((long)c * NH + h) * (HD * HD);
    #pragma unroll
    for (int i = 0; i < 8; i++) {
        float4 r0 = make_float4(acc[i][0], acc[i][1], acc[i][2], acc[i][3]);
        float4 r1 = make_float4(acc[i][4], acc[i][5], acc[i][6], acc[i][7]);
        *(float4*)&out[(ty*8 + i) * 128 + tx*8]     = r0;
        *(float4*)&out[(ty*8 + i) * 128 + tx*8 + 4] = r1;
    }
}

// ---------------------------------------------------------------------------
// Exclusive prefix over chunks: S[c] = sum_{j<c} KV[j]   (per h,d,e element)
// ---------------------------------------------------------------------------
__global__ void prefix_kernel(const float* __restrict__ KV, float* __restrict__ S)
{
    const int idx = blockIdx.x * 256 + threadIdx.x;   // 0 .. 262143 (h*16384 + d*128 + e)
    float acc = 0.f;
    #pragma unroll 4
    for (int c = 0; c < NCHUNK; c++) {
        S[(long)c * (NH * HD * HD) + idx] = acc;
        acc += KV[(long)c * (NH * HD * HD) + idx];
    }
}

// ---------------------------------------------------------------------------
// Per-(chunk, head) attention:
//   scT[j][i] = (i>=j) ? sum_d q[i][d] k[j][d] : 0
//   o[i][e]   = sum_j scT[j][i] v[j][e]  +  sum_d q[i][d] S[d][e]
// grid(NCHUNK, NH), 256 threads, dyn smem = 3 * 64KB
// ---------------------------------------------------------------------------
__global__ __launch_bounds__(256, 1)
void attn_chunk_kernel(const float* __restrict__ qkv, const float* __restrict__ S,
                       float* __restrict__ O)
{
    extern __shared__ float sm[];
    float* sQ = sm;             // qT [d][i]
    float* sB = sm + 16384;     // kT [d][j], then v [j][e]
    float* sC = sm + 32768;     // scoresT [j][i], then S [d][e]

    const int c = blockIdx.x, h = blockIdx.y;
    const int t0 = c * CHUNK;
    const int tid = threadIdx.x, tx = tid & 15, ty = tid >> 4;

    const float* qg = qkv + (long)t0 * QKV_W + h * HD;
    const float* kg = qg + INNER;
    const float* vg = qg + 2 * INNER;

    // load qT, kT (transpose on store)
    #pragma unroll
    for (int r = 0; r < 16; r++) {
        int idx = r * 256 + tid;
        int i  = idx >> 5;
        int dd = (idx & 31) << 2;
        float4 q4 = *(const float4*)(qg + (long)i * QKV_W + dd);
        float4 k4 = *(const float4*)(kg + (long)i * QKV_W + dd);
        sQ[(dd+0)*128 + i] = q4.x; sQ[(dd+1)*128 + i] = q4.y;
        sQ[(dd+2)*128 + i] = q4.z; sQ[(dd+3)*128 + i] = q4.w;
        sB[(dd+0)*128 + i] = k4.x; sB[(dd+1)*128 + i] = k4.y;
        sB[(dd+2)*128 + i] = k4.z; sB[(dd+3)*128 + i] = k4.w;
    }
    __syncthreads();

    // GEMM1: scT[j][i] with causal mask (keep i >= j)
    {
        float acc[8][8];
        #pragma unroll
        for (int a = 0; a < 8; a++)
            #pragma unroll
            for (int b = 0; b < 8; b++) acc[a][b] = 0.f;

        for (int d = 0; d < 128; d++) {
            float a[8], b[8];
            *(float4*)&a[0] = *(const float4*)&sB[d * 128 + ty*8];      // k rows (j)
            *(float4*)&a[4] = *(const float4*)&sB[d * 128 + ty*8 + 4];
            *(float4*)&b[0] = *(const float4*)&sQ[d * 128 + tx*8];      // q rows (i)
            *(float4*)&b[4] = *(const float4*)&sQ[d * 128 + tx*8 + 4];
            #pragma unroll
            for (int jj = 0; jj < 8; jj++)
                #pragma unroll
                for (int ii = 0; ii < 8; ii++)
                    acc[jj][ii] += a[jj] * b[ii];
        }
        __syncthreads();   // kT reads done; sC free to write
        #pragma unroll
        for (int jj = 0; jj < 8; jj++) {
            int j = ty*8 + jj;
            #pragma unroll
            for (int ii = 0; ii < 8; ii++) {
                int i = tx*8 + ii;
                sC[j * 128 + i] = (i >= j) ? acc[jj][ii] : 0.f;
            }
        }
    }
    __syncthreads();

    // overwrite sB with v (natural [j][e])
    #pragma unroll
    for (int r = 0; r < 16; r++) {
        int idx = r * 256 + tid;
        int row = idx >> 5;
        int col = (idx & 31) << 2;
        *(float4*)&sB[row * 128 + col] = *(const float4*)(vg + (long)row * QKV_W + col);
    }
    __syncthreads();

    // GEMM2: o[i][e] = sum_j scT[j][i] * v[j][e]
    float o[8][8];
    #pragma unroll
    for (int a = 0; a < 8; a++)
        #pragma unroll
        for (int b = 0; b < 8; b++) o[a][b] = 0.f;

    for (int j = 0; j < 128; j++) {
        float a[8], b[8];
        *(float4*)&a[0] = *(const float4*)&sC[j * 128 + ty*8];
        *(float4*)&a[4] = *(const float4*)&sC[j * 128 + ty*8 + 4];
        *(float4*)&b[0] = *(const float4*)&sB[j * 128 + tx*8];
        *(float4*)&b[4] = *(const float4*)&sB[j * 128 + tx*8 + 4];
        #pragma unroll
        for (int ii = 0; ii < 8; ii++)
            #pragma unroll
            for (int ee = 0; ee < 8; ee++)
                o[ii][ee] += a[ii] * b[ee];
    }
    __syncthreads();

    // overwrite sC with S (natural [d][e])
    const float* Sg = S + ((long)c * NH + h) * (HD * HD);
    #pragma unroll
    for (int r = 0; r < 16; r++) {
        int idx = r * 256 + tid;
        int row = idx >> 5;
        int col = (idx & 31) << 2;
        *(float4*)&sC[row * 128 + col] = *(const float4*)(Sg + row * 128 + col);
    }
    __syncthreads();

    // GEMM3: o[i][e] += sum_d qT[d][i] * S[d][e]
    for (int d = 0; d < 128; d++) {
        float a[8], b[8];
        *(float4*)&a[0] = *(const float4*)&sQ[d * 128 + ty*8];
        *(float4*)&a[4] = *(const float4*)&sQ[d * 128 + ty*8 + 4];
        *(float4*)&b[0] = *(const float4*)&sC[d * 128 + tx*8];
        *(float4*)&b[4] = *(const float4*)&sC[d * 128 + tx*8 + 4];
        #pragma unroll
        for (int ii = 0; ii < 8; ii++)
            #pragma unroll
            for (int ee = 0; ee < 8; ee++)
                o[ii][ee] += a[ii] * b[ee];
    }

    // write O[t][h*128 + e]
    #pragma unroll
    for (int ii = 0; ii < 8; ii++) {
        float* Op = O + (long)(t0 + ty*8 + ii) * INNER + h * HD + tx*8;
        *(float4*)(Op)     = make_float4(o[ii][0], o[ii][1], o[ii][2], o[ii][3]);
        *(float4*)(Op + 4) = make_float4(o[ii][4], o[ii][5], o[ii][6], o[ii][7]);
    }
}

// ---------------------------------------------------------------------------
// Per-token g-norm + sigmoid gate: G[t] = sigmoid(G[t]) * rmsnorm(O[t]) * gw
// grid(T), 256 threads; in-place over g_gate
// ---------------------------------------------------------------------------
__global__ __launch_bounds__(256)
void gate_norm_kernel(const float* __restrict__ O, float* __restrict__ G,
                      const float* __restrict__ gw)
{
    const int t = blockIdx.x;
    const int tid = threadIdx.x;
    const float* orow = O + (long)t * INNER;
    float* grow = G + (long)t * INNER;

    float4 o0 = *(const float4*)(orow + tid * 4);
    float4 o1 = *(const float4*)(orow + 1024 + tid * 4);

    float s = o0.x*o0.x + o0.y*o0.y + o0.z*o0.z + o0.w*o0.w
            + o1.x*o1.x + o1.y*o1.y + o1.z*o1.z + o1.w*o1.w;
    #pragma unroll
    for (int o = 16; o; o >>= 1) s += __shfl_xor_sync(0xffffffffu, s, o);
    __shared__ float red[8];
    if ((tid & 31) == 0) red[tid >> 5] = s;
    __syncthreads();
    float tot = 0.f;
    #pragma unroll
    for (int w = 0; w < 8; w++) tot += red[w];
    const float rs = rsqrtf(tot * (1.f / 2048.f) + EPS);

    float4 g0 = *(const float4*)(grow + tid * 4);
    float4 g1 = *(const float4*)(grow + 1024 + tid * 4);
    float4 w0 = *(const float4*)(gw + tid * 4);
    float4 w1 = *(const float4*)(gw + 1024 + tid * 4);

    float4 r0, r1;
    r0.x = (1.f / (1.f + expf(-g0.x))) * o0.x * rs * w0.x;
    r0.y = (1.f / (1.f + expf(-g0.y))) * o0.y * rs * w0.y;
    r0.z = (1.f / (1.f + expf(-g0.z))) * o0.z * rs * w0.z;
    r0.w = (1.f / (1.f + expf(-g0.w))) * o0.w * rs * w0.w;
    r1.x = (1.f / (1.f + expf(-g1.x))) * o1.x * rs * w1.x;
    r1.y = (1.f / (1.f + expf(-g1.y))) * o1.y * rs * w1.y;
    r1.z = (1.f / (1.f + expf(-g1.z))) * o1.z * rs * w1.z;
    r1.w = (1.f / (1.f + expf(-g1.w))) * o1.w * rs * w1.w;

    *(float4*)(grow + tid * 4)        = r0;
    *(float4*)(grow + 1024 + tid * 4) = r1;
}

// ---------------------------------------------------------------------------
// Launch
// ---------------------------------------------------------------------------
extern "C" void kernel_launch(void* const* d_in, const int* in_sizes, int n_in,
                              void* d_out, int out_size)
{
    const float* x    = (const float*)d_in[0];   // [8192, 2048]
    const int*   pos  = (const int*)  d_in[1];   // [8192]
    const float* Wqkv = (const float*)d_in[2];   // [2048, 6144]
    const float* qw   = (const float*)d_in[3];   // [128]
    const float* kw   = (const float*)d_in[4];   // [128]
    const float* Wg   = (const float*)d_in[5];   // [2048, 2048]
    const float* gw   = (const float*)d_in[6];   // [2048]
    const float* Wo   = (const float*)d_in[7];   // [2048, 2048]
    float* out = (float*)d_out;                  // [8192, 2048]

    float* qkv;  cudaGetSymbolAddress((void**)&qkv,  g_qkv);
    float* gate; cudaGetSymbolAddress((void**)&gate, g_gate);
    float* o;    cudaGetSymbolAddress((void**)&o,    g_o);
    float* kvp;  cudaGetSymbolAddress((void**)&kvp,  g_kvp);
    float* S;    cudaGetSymbolAddress((void**)&S,    g_S);

    cudaFuncSetAttribute(kv_outer_kernel,
                         cudaFuncAttributeMaxDynamicSharedMemorySize, 2 * 65536);
    cudaFuncSetAttribute(attn_chunk_kernel,
                         cudaFuncAttributeMaxDynamicSharedMemorySize, 3 * 65536);

    // 1. qkv = silu(x @ Wqkv)
    sgemm128<1><<<dim3(QKV_W / 128, T_TOK / 128), 256>>>(x, Wqkv, qkv, T_TOK, QKV_W, HID);
    // 2. gate = x @ Wg
    sgemm128<0><<<dim3(INNER / 128, T_TOK / 128), 256>>>(x, Wg, gate, T_TOK, INNER, HID);
    // 3. per-head rmsnorm + rope (+ q scale), in place
    qk_rope_kernel<<<dim3(T_TOK, NH), 64>>>(qkv, pos, qw, kw);
    // 4. per-chunk KV outer products
    kv_outer_kernel<<<dim3(NCHUNK, NH), 256, 2 * 65536>>>(qkv, kvp);
    // 5. exclusive prefix over chunks -> per-chunk state S
    prefix_kernel<<<(NH * HD * HD) / 256, 256>>>(kvp, S);
    // 6. intra-chunk masked attention + inter-chunk q@S
    attn_chunk_kernel<<<dim3(NCHUNK, NH), 256, 3 * 65536>>>(qkv, S, o);
    // 7. g-norm + sigmoid gating (in place over gate)
    gate_norm_kernel<<<T_TOK, 256>>>(o, gate, gw);
    // 8. out = gated @ Wo
    sgemm128<0><<<dim3(HID / 128, T_TOK / 128), 256>>>(gate, Wo, out, T_TOK, HID, INNER);
}

// round 2
// speedup vs baseline: 1.0006x; 1.0006x over previous
#include <cuda_runtime.h>
#include <cuda_bf16.h>
#include <math.h>

// ---------------------------------------------------------------------------
// Problem constants
// ---------------------------------------------------------------------------
#define T_TOK   8192
#define HID     2048
#define NH      16
#define HD      128
#define INNER   2048          // NH*HD
#define QKV_W   6144          // 3*INNER
#define NCHUNK  64            // T/128
#define CHUNK   128
#define EPS     1e-5f
#define QSCALE  0.08838834764831845f   // 128^-0.5

// ---------------------------------------------------------------------------
// Device scratch (static globals: allocation-free rule)
// ---------------------------------------------------------------------------
__device__ float g_qkv [T_TOK * QKV_W];            // 192 MiB: silu(x@Wqkv), q/k rope'd in place
__device__ float g_gate[T_TOK * INNER];            // 64 MiB: x@Wg, then overwritten with gated value
__device__ float g_o   [T_TOK * INNER];            // 64 MiB: attention output
__device__ float g_kvp [NCHUNK * NH * HD * HD];    // 64 MiB: per-chunk KV outer products
__device__ float g_S   [NCHUNK * NH * HD * HD];    // 64 MiB: exclusive prefix state per chunk

// ---------------------------------------------------------------------------
// Generic fp32 SGEMM: C[M,N] = act(A[M,K] @ B[K,N])
// 128x128 block tile, BK=16, 256 threads, 8x8 microtile, prefetched
// ACT: 0 = none, 1 = silu
// ---------------------------------------------------------------------------
template<int ACT>
__global__ __launch_bounds__(256, 2)
void sgemm128(const float* __restrict__ A, const float* __restrict__ B,
              float* __restrict__ C, int M, int N, int K)
{
    __shared__ float As[16][128];   // transposed: As[k][m]
    __shared__ float Bs[16][128];   // natural:    Bs[k][n]

    const int bm = blockIdx.y * 128;
    const int bn = blockIdx.x * 128;
    const int tid = threadIdx.x;
    const int tx = tid & 15;        // 0..15 -> N microtile
    const int ty = tid >> 4;        // 0..15 -> M microtile

    // A tile loader: 128 rows x 16 cols, each thread 2 float4
    const int a_row = tid >> 2;            // 0..63 (and +64)
    const int a_col = (tid & 3) << 2;      // 0,4,8,12
    // B tile loader: 16 rows x 128 cols, each thread 2 float4
    const int b_row = tid >> 5;            // 0..7 (and +8)
    const int b_col = (tid & 31) << 2;

    const float* Ap = A + (long)(bm + a_row) * K + a_col;
    const float* Ap2 = Ap + (long)64 * K;
    const float* Bp = B + (long)b_row * N + bn + b_col;
    const float* Bp2 = Bp + (long)8 * N;

    float4 a0 = *(const float4*)(Ap);
    float4 a1 = *(const float4*)(Ap2);
    float4 b0 = *(const float4*)(Bp);
    float4 b1 = *(const float4*)(Bp2);

    float acc[8][8];
    #pragma unroll
    for (int i = 0; i < 8; i++)
        #pragma unroll
        for (int j = 0; j < 8; j++) acc[i][j] = 0.f;

    for (int k0 = 0; k0 < K; k0 += 16) {
        // store staged tile
        As[a_col+0][a_row]    = a0.x; As[a_col+1][a_row]    = a0.y;
        As[a_col+2][a_row]    = a0.z; As[a_col+3][a_row]    = a0.w;
        As[a_col+0][a_row+64] = a1.x; As[a_col+1][a_row+64] = a1.y;
        As[a_col+2][a_row+64] = a1.z; As[a_col+3][a_row+64] = a1.w;
        *(float4*)&Bs[b_row][b_col]   = b0;
        *(float4*)&Bs[b_row+8][b_col] = b1;
        __syncthreads();

        // prefetch next tile while computing this one
        if (k0 + 16 < K) {
            a0 = *(const float4*)(Ap  + k0 + 16);
            a1 = *(const float4*)(Ap2 + k0 + 16);
            b0 = *(const float4*)(Bp  + (long)(k0 + 16) * N);
            b1 = *(const float4*)(Bp2 + (long)(k0 + 16) * N);
        }

        #pragma unroll
        for (int kk = 0; kk < 16; kk++) {
            float a[8], b[8];
            *(float4*)&a[0] = *(const float4*)&As[kk][ty*8];
            *(float4*)&a[4] = *(const float4*)&As[kk][ty*8+4];
            *(float4*)&b[0] = *(const float4*)&Bs[kk][tx*8];
            *(float4*)&b[4] = *(const float4*)&Bs[kk][tx*8+4];
            #pragma unroll
            for (int i = 0; i < 8; i++)
                #pragma unroll
                for (int j = 0; j < 8; j++)
                    acc[i][j] += a[i] * b[j];
        }
        __syncthreads();
    }

    // epilogue
    #pragma unroll
    for (int i = 0; i < 8; i++) {
        float* Cp = C + (long)(bm + ty*8 + i) * N + bn + tx*8;
        float4 r0, r1;
        float v[8];
        #pragma unroll
        for (int j = 0; j < 8; j++) {
            float x = acc[i][j];
            if (ACT == 1) x = x / (1.f + expf(-x));   // silu
            v[j] = x;
        }
        r0.x = v[0]; r0.y = v[1]; r0.z = v[2]; r0.w = v[3];
        r1.x = v[4]; r1.y = v[5]; r1.z = v[6]; r1.w = v[7];
        *(float4*)(Cp)     = r0;
        *(float4*)(Cp + 4) = r1;
    }
}

// ---------------------------------------------------------------------------
// Per-(token, head) RMSNorm + RoPE (+ q scale), in place on g_qkv
// grid(T, H), 64 threads; thread j handles dims j and j+64 (rope pair)
// ---------------------------------------------------------------------------
__global__ void qk_rope_kernel(float* __restrict__ qkv,
                               const int* __restrict__ pos,
                               const float* __restrict__ qw,
                               const float* __restrict__ kw)
{
    const int t = blockIdx.x, h = blockIdx.y;
    const int j = threadIdx.x;              // 0..63
    float* qp = qkv + (long)t * QKV_W + h * HD;
    float* kp = qp + INNER;

    float q1 = qp[j], q2 = qp[j + 64];
    float k1 = kp[j], k2 = kp[j + 64];

    float sq = q1*q1 + q2*q2;
    float sk = k1*k1 + k2*k2;
    #pragma unroll
    for (int o = 16; o; o >>= 1) {
        sq += __shfl_xor_sync(0xffffffffu, sq, o);
        sk += __shfl_xor_sync(0xffffffffu, sk, o);
    }
    __shared__ float red[4];
    const int w = j >> 5, lane = j & 31;
    if (lane == 0) { red[w] = sq; red[2 + w] = sk; }
    __syncthreads();
    const float rq = rsqrtf((red[0] + red[1]) * (1.f / 128.f) + EPS);
    const float rk = rsqrtf((red[2] + red[3]) * (1.f / 128.f) + EPS);

    q1 = q1 * rq * qw[j]; q2 = q2 * rq * qw[j + 64];
    k1 = k1 * rk * kw[j]; k2 = k2 * rk * kw[j + 64];

    const float inv = powf(600000.0f, -(float)j * (1.0f / 64.0f));
    const float ang = (float)pos[t] * inv;
    float s, c;
    sincosf(ang, &s, &c);

    qp[j]      = (q1 * c - q2 * s) * QSCALE;
    qp[j + 64] = (q2 * c + q1 * s) * QSCALE;
    kp[j]      =  k1 * c - k2 * s;
    kp[j + 64] =  k2 * c + k1 * s;
}

// ---------------------------------------------------------------------------
// Per-(chunk, head) KV outer product: KV[d][e] = sum_j k[j][d] * v[j][e]
// grid(NCHUNK, NH), 256 threads, dyn smem = 2 * 64KB
// ---------------------------------------------------------------------------
__global__ __launch_bounds__(256, 1)
void kv_outer_kernel(const float* __restrict__ qkv, float* __restrict__ KV)
{
    extern __shared__ float sm[];
    float* sK = sm;            // [j][d]
    float* sV = sm + 16384;    // [j][e]

    const int c = blockIdx.x, h = blockIdx.y;
    const int t0 = c * CHUNK;
    const int tid = threadIdx.x, tx = tid & 15, ty = tid >> 4;

    const float* kg = qkv + (long)t0 * QKV_W + h * HD + INNER;
    const float* vg = kg + INNER;

    #pragma unroll
    for (int r = 0; r < 16; r++) {
        int idx = r * 256 + tid;            // 0..4095
        int row = idx >> 5;
        int col = (idx & 31) << 2;
        *(float4*)&sK[row * 128 + col] = *(const float4*)(kg + (long)row * QKV_W + col);
        *(float4*)&sV[row * 128 + col] = *(const float4*)(vg + (long)row * QKV_W + col);
    }
    __syncthreads();

    float acc[8][8];
    #pragma unroll
    for (int i = 0; i < 8; i++)
        #pragma unroll
        for (int j = 0; j < 8; j++) acc[i][j] = 0.f;

    for (int j = 0; j < 128; j++) {
        float a[8], b[8];
        *(float4*)&a[0] = *(const float4*)&sK[j * 128 + ty*8];
        *(float4*)&a[4] = *(const float4*)&sK[j * 128 + ty*8 + 4];
        *(float4*)&b[0] = *(const float4*)&sV[j * 128 + tx*8];
        *(float4*)&b[4] = *(const float4*)&sV[j * 128 + tx*8 + 4];
        #pragma unroll
        for (int i = 0; i < 8; i++)
            #pragma unroll
            for (int e = 0; e < 8; e++)
                acc[i][e] += a[i] * b[e];
    }

    float* out = KV + ((long)c * NH + h) * (HD * HD);
    #pragma unroll
    for (int i = 0; i < 8; i++) {
        float4 r0 = make_float4(acc[i][0], acc[i][1], acc[i][2], acc[i][3]);
        float4 r1 = make_float4(acc[i][4], acc[i][5], acc[i][6], acc[i][7]);
        *(float4*)&out[(ty*8 + i) * 128 + tx*8]     = r0;
        *(float4*)&out[(ty*8 + i) * 128 + tx*8 + 4] = r1;
    }
}

// ---------------------------------------------------------------------------
// Exclusive prefix over chunks: S[c] = sum_{j<c} KV[j]   (per h,d,e element)
// ---------------------------------------------------------------------------
__global__ void prefix_kernel(const float* __restrict__ KV, float* __restrict__ S)
{
    const int idx = blockIdx.x * 256 + threadIdx.x;   // 0 .. 262143 (h*16384 + d*128 + e)
    float acc = 0.f;
    #pragma unroll 4
    for (int c = 0; c < NCHUNK; c++) {
        S[(long)c * (NH * HD * HD) + idx] = acc;
        acc += KV[(long)c * (NH * HD * HD) + idx];
    }
}

// ---------------------------------------------------------------------------
// Per-(chunk, head) attention:
//   scT[j][i] = (i>=j) ? sum_d q[i][d] k[j][d] : 0
//   o[i][e]   = sum_j scT[j][i] v[j][e]  +  sum_d q[i][d] S[d][e]
// grid(NCHUNK, NH), 256 threads, dyn smem = 3 * 64KB
// ---------------------------------------------------------------------------
__global__ __launch_bounds__(256, 1)
void attn_chunk_kernel(const float* __restrict__ qkv, const float* __restrict__ S,
                       float* __restrict__ O)
{
    extern __shared__ float sm[];
    float* sQ = sm;             // qT [d][i]
    float* sB = sm + 16384;     // kT [d][j], then v [j][e]
    float* sC = sm + 32768;     // scoresT [j][i], then S [d][e]

    const int c = blockIdx.x, h = blockIdx.y;
    const int t0 = c * CHUNK;
    const int tid = threadIdx.x, tx = tid & 15, ty = tid >> 4;

    const float* qg = qkv + (long)t0 * QKV_W + h * HD;
    const float* kg = qg + INNER;
    const float* vg = qg + 2 * INNER;

    // load qT, kT (transpose on store)
    #pragma unroll
    for (int r = 0; r < 16; r++) {
        int idx = r * 256 + tid;
        int i  = idx >> 5;
        int dd = (idx & 31) << 2;
        float4 q4 = *(const float4*)(qg + (long)i * QKV_W + dd);
        float4 k4 = *(const float4*)(kg + (long)i * QKV_W + dd);
        sQ[(dd+0)*128 + i] = q4.x; sQ[(dd+1)*128 + i] = q4.y;
        sQ[(dd+2)*128 + i] = q4.z; sQ[(dd+3)*128 + i] = q4.w;
        sB[(dd+0)*128 + i] = k4.x; sB[(dd+1)*128 + i] = k4.y;
        sB[(dd+2)*128 + i] = k4.z; sB[(dd+3)*128 + i] = k4.w;
    }
    __syncthreads();

    // GEMM1: scT[j][i] with causal mask (keep i >= j)
    {
        float acc[8][8];
        #pragma unroll
        for (int a = 0; a < 8; a++)
            #pragma unroll
            for (int b = 0; b < 8; b++) acc[a][b] = 0.f;

        for (int d = 0; d < 128; d++) {
            float a[8], b[8];
            *(float4*)&a[0] = *(const float4*)&sB[d * 128 + ty*8];      // k rows (j)
            *(float4*)&a[4] = *(const float4*)&sB[d * 128 + ty*8 + 4];
            *(float4*)&b[0] = *(const float4*)&sQ[d * 128 + tx*8];      // q rows (i)
            *(float4*)&b[4] = *(const float4*)&sQ[d * 128 + tx*8 + 4];
            #pragma unroll
            for (int jj = 0; jj < 8; jj++)
                #pragma unroll
                for (int ii = 0; ii < 8; ii++)
                    acc[jj][ii] += a[jj] * b[ii];
        }
        __syncthreads();   // kT reads done; sC free to write
        #pragma unroll
        for (int jj = 0; jj < 8; jj++) {
            int j = ty*8 + jj;
            #pragma unroll
            for (int ii = 0; ii < 8; ii++) {
                int i = tx*8 + ii;
                sC[j * 128 + i] = (i >= j) ? acc[jj][ii] : 0.f;
            }
        }
    }
    __syncthreads();

    // overwrite sB with v (natural [j][e])
    #pragma unroll
    for (int r = 0; r < 16; r++) {
        int idx = r * 256 + tid;
        int row = idx >> 5;
        int col = (idx & 31) << 2;
        *(float4*)&sB[row * 128 + col] = *(const float4*)(vg + (long)row * QKV_W + col);
    }
    __syncthreads();

    // GEMM2: o[i][e] = sum_j scT[j][i] * v[j][e]
    float o[8][8];
    #pragma unroll
    for (int a = 0; a < 8; a++)
        #pragma unroll
        for (int b = 0; b < 8; b++) o[a][b] = 0.f;

    for (int j = 0; j < 128; j++) {
        float a[8], b[8];
        *(float4*)&a[0] = *(const float4*)&sC[j * 128 + ty*8];
        *(float4*)&a[4] = *(const float4*)&sC[j * 128 + ty*8 + 4];
        *(float4*)&b[0] = *(const float4*)&sB[j * 128 + tx*8];
        *(float4*)&b[4] = *(const float4*)&sB[j * 128 + tx*8 + 4];
        #pragma unroll
        for (int ii = 0; ii < 8; ii++)
            #pragma unroll
            for (int ee = 0; ee < 8; ee++)
                o[ii][ee] += a[ii] * b[ee];
    }
    __syncthreads();

    // overwrite sC with S (natural [d][e])
    const float* Sg = S + ((long)c * NH + h) * (HD * HD);
    #pragma unroll
    for (int r = 0; r < 16; r++) {
        int idx = r * 256 + tid;
        int row = idx >> 5;
        int col = (idx & 31) << 2;
        *(float4*)&sC[row * 128 + col] = *(const float4*)(Sg + row * 128 + col);
    }
    __syncthreads();

    // GEMM3: o[i][e] += sum_d qT[d][i] * S[d][e]
    for (int d = 0; d < 128; d++) {
        float a[8], b[8];
        *(float4*)&a[0] = *(const float4*)&sQ[d * 128 + ty*8];
        *(float4*)&a[4] = *(const float4*)&sQ[d * 128 + ty*8 + 4];
        *(float4*)&b[0] = *(const float4*)&sC[d * 128 + tx*8];
        *(float4*)&b[4] = *(const float4*)&sC[d * 128 + tx*8 + 4];
        #pragma unroll
        for (int ii = 0; ii < 8; ii++)
            #pragma unroll
            for (int ee = 0; ee < 8; ee++)
                o[ii][ee] += a[ii] * b[ee];
    }

    // write O[t][h*128 + e]
    #pragma unroll
    for (int ii = 0; ii < 8; ii++) {
        float* Op = O + (long)(t0 + ty*8 + ii) * INNER + h * HD + tx*8;
        *(float4*)(Op)     = make_float4(o[ii][0], o[ii][1], o[ii][2], o[ii][3]);
        *(float4*)(Op + 4) = make_float4(o[ii][4], o[ii][5], o[ii][6], o[ii][7]);
    }
}

// ---------------------------------------------------------------------------
// Per-token g-norm + sigmoid gate: G[t] = sigmoid(G[t]) * rmsnorm(O[t]) * gw
// grid(T), 256 threads; in-place over g_gate
// ---------------------------------------------------------------------------
__global__ __launch_bounds__(256)
void gate_norm_kernel(const float* __restrict__ O, float* __restrict__ G,
                      const float* __restrict__ gw)
{
    const int t = blockIdx.x;
    const int tid = threadIdx.x;
    const float* orow = O + (long)t * INNER;
    float* grow = G + (long)t * INNER;

    float4 o0 = *(const float4*)(orow + tid * 4);
    float4 o1 = *(const float4*)(orow + 1024 + tid * 4);

    float s = o0.x*o0.x + o0.y*o0.y + o0.z*o0.z + o0.w*o0.w
            + o1.x*o1.x + o1.y*o1.y + o1.z*o1.z + o1.w*o1.w;
    #pragma unroll
    for (int o = 16; o; o >>= 1) s += __shfl_xor_sync(0xffffffffu, s, o);
    __shared__ float red[8];
    if ((tid & 31) == 0) red[tid >> 5] = s;
    __syncthreads();
    float tot = 0.f;
    #pragma unroll
    for (int w = 0; w < 8; w++) tot += red[w];
    const float rs = rsqrtf(tot * (1.f / 2048.f) + EPS);

    float4 g0 = *(const float4*)(grow + tid * 4);
    float4 g1 = *(const float4*)(grow + 1024 + tid * 4);
    float4 w0 = *(const float4*)(gw + tid * 4);
    float4 w1 = *(const float4*)(gw + 1024 + tid * 4);

    float4 r0, r1;
    r0.x = (1.f / (1.f + expf(-g0.x))) * o0.x * rs * w0.x;
    r0.y = (1.f / (1.f + expf(-g0.y))) * o0.y * rs * w0.y;
    r0.z = (1.f / (1.f + expf(-g0.z))) * o0.z * rs * w0.z;
    r0.w = (1.f / (1.f + expf(-g0.w))) * o0.w * rs * w0.w;
    r1.x = (1.f / (1.f + expf(-g1.x))) * o1.x * rs * w1.x;
    r1.y = (1.f / (1.f + expf(-g1.y))) * o1.y * rs * w1.y;
    r1.z = (1.f / (1.f + expf(-g1.z))) * o1.z * rs * w1.z;
    r1.w = (1.f / (1.f + expf(-g1.w))) * o1.w * rs * w1.w;

    *(float4*)(grow + tid * 4)        = r0;
    *(float4*)(grow + 1024 + tid * 4) = r1;
}

// ---------------------------------------------------------------------------
// Launch
// ---------------------------------------------------------------------------
extern "C" void kernel_launch(void* const* d_in, const int* in_sizes, int n_in,
                              void* d_out, int out_size)
{
    const float* x    = (const float*)d_in[0];   // [8192, 2048]
    const int*   pos  = (const int*)  d_in[1];   // [8192]
    const float* Wqkv = (const float*)d_in[2];   // [2048, 6144]
    const float* qw   = (const float*)d_in[3];   // [128]
    const float* kw   = (const float*)d_in[4];   // [128]
    const float* Wg   = (const float*)d_in[5];   // [2048, 2048]
    const float* gw   = (const float*)d_in[6];   // [2048]
    const float* Wo   = (const float*)d_in[7];   // [2048, 2048]
    float* out = (float*)d_out;                  // [8192, 2048]

    float* qkv;  cudaGetSymbolAddress((void**)&qkv,  g_qkv);
    float* gate; cudaGetSymbolAddress((void**)&gate, g_gate);
    float* o;    cudaGetSymbolAddress((void**)&o,    g_o);
    float* kvp;  cudaGetSymbolAddress((void**)&kvp,  g_kvp);
    float* S;    cudaGetSymbolAddress((void**)&S,    g_S);

    cudaFuncSetAttribute(kv_outer_kernel,
                         cudaFuncAttributeMaxDynamicSharedMemorySize, 2 * 65536);
    cudaFuncSetAttribute(attn_chunk_kernel,
                         cudaFuncAttributeMaxDynamicSharedMemorySize, 3 * 65536);

    // 1. qkv = silu(x @ Wqkv)
    sgemm128<1><<<dim3(QKV_W / 128, T_TOK / 128), 256>>>(x, Wqkv, qkv, T_TOK, QKV_W, HID);
    // 2. gate = x @ Wg
    sgemm128<0><<<dim3(INNER / 128, T_TOK / 128), 256>>>(x, Wg, gate, T_TOK, INNER, HID);
    // 3. per-head rmsnorm + rope (+ q scale), in place
    qk_rope_kernel<<<dim3(T_TOK, NH), 64>>>(qkv, pos, qw, kw);
    // 4. per-chunk KV outer products
    kv_outer_kernel<<<dim3(NCHUNK, NH), 256, 2 * 65536>>>(qkv, kvp);
    // 5. exclusive prefix over chunks -> per-chunk state S
    prefix_kernel<<<(NH * HD * HD) / 256, 256>>>(kvp, S);
    // 6. intra-chunk masked attention + inter-chunk q@S
    attn_chunk_kernel<<<dim3(NCHUNK, NH), 256, 3 * 65536>>>(qkv, S, o);
    // 7. g-norm + sigmoid gating (in place over gate)
    gate_norm_kernel<<<T_TOK, 256>>>(o, gate, gw);
    // 8. out = gated @ Wo
    sgemm128<0><<<dim3(HID / 128, T_TOK / 128), 256>>>(gate, Wo, out, T_TOK, HID, INNER);
}